// round 15
// baseline (speedup 1.0000x reference)
#include <cuda_runtime.h>
#include <math.h>

#define D 512
#define V 17
#define MAX_SEGS 64
#define EPAD 20
#define TPB 512

// Scratch (allocation-free, graph-safe, zero-initialized at module load;
// g_done/g_ack are reset to 0 by the kernel itself before exit every launch).
__device__ float g_midT[D * EPAD];         // finalized gelu-mid, transposed+padded
__device__ int   g_hist[MAX_SEGS][V];      // per-segment token counts
__device__ int   g_done;                   // producers(64) + consumer-hists(64)
__device__ int   g_ack;                    // consumers past the wait

// ---------------------------------------------------------------------------
// fused: CTAs 0..63 (producers): full-K GEMM1 -> g_midT, arrive.
//        CTAs 64..127 (consumers): histogram -> g_hist, arrive, wait for 128
//        arrivals, then GEMM2 + segment mix + store for their 8 columns.
// 128 CTAs @ 1/SM: all co-resident (wave 1), dependency graph acyclic.
// ---------------------------------------------------------------------------
__global__ void __launch_bounds__(TPB, 1)
fused(const float* __restrict__ E,  const float* __restrict__ W1,
      const float* __restrict__ b1, const float* __restrict__ W2,
      const float* __restrict__ b2, const int* __restrict__ tok,
      const int* __restrict__ cu,   float* __restrict__ out, int n_segs) {
    __shared__ float etr[D * EPAD];        // 40960B: stage + reduction buffer
    __shared__ int   cnt[16 * 32];         // 2048B: per-warp histograms
    __shared__ float Ht[V * 8];            // 544B
    __shared__ float fcs[MAX_SEGS * 18];   // 4608B
    __shared__ float inv[MAX_SEGS];        // 256B   (total 48416 <= 49152)

    const int bid = blockIdx.x;
    const int tid = threadIdx.x;

    if (bid < 64) {
        // ================= producer: GEMM1 =================
        const int jl = tid & 7;
        const int ty = tid >> 3;
        const int jbase = bid * 8;

        const float4* E4 = (const float4*)E;
#pragma unroll
        for (int r = 0; r < 4; r++) {
            const int i = r * TPB + tid;
            const float4 e = E4[i];
            const int v = i >> 7;
            const int k = (i & 127) * 4;
            etr[(k + 0) * EPAD + v] = e.x;
            etr[(k + 1) * EPAD + v] = e.y;
            etr[(k + 2) * EPAD + v] = e.z;
            etr[(k + 3) * EPAD + v] = e.w;
        }
        if (tid < V * 128 - 4 * TPB) {
            const int i = 4 * TPB + tid;
            const float4 e = E4[i];
            const int v = i >> 7;
            const int k = (i & 127) * 4;
            etr[(k + 0) * EPAD + v] = e.x;
            etr[(k + 1) * EPAD + v] = e.y;
            etr[(k + 2) * EPAD + v] = e.z;
            etr[(k + 3) * EPAD + v] = e.w;
        }
        __syncthreads();

        float acc[V];
#pragma unroll
        for (int v = 0; v < V; v++) acc[v] = 0.0f;

        const float* wp = W1 + (size_t)(ty * 8) * D + jbase + jl;
        float w[8];
#pragma unroll
        for (int kk = 0; kk < 8; kk++) w[kk] = wp[kk * D];

#pragma unroll
        for (int kk = 0; kk < 8; kk++) {
            const float* er = &etr[(ty * 8 + kk) * EPAD];
            const float4 e0 = *(const float4*)(er);
            const float4 e1 = *(const float4*)(er + 4);
            const float4 e2 = *(const float4*)(er + 8);
            const float4 e3 = *(const float4*)(er + 12);
            const float  ee = er[16];
            const float  wv = w[kk];
            acc[0]  += e0.x * wv;  acc[1]  += e0.y * wv;
            acc[2]  += e0.z * wv;  acc[3]  += e0.w * wv;
            acc[4]  += e1.x * wv;  acc[5]  += e1.y * wv;
            acc[6]  += e1.z * wv;  acc[7]  += e1.w * wv;
            acc[8]  += e2.x * wv;  acc[9]  += e2.y * wv;
            acc[10] += e2.z * wv;  acc[11] += e2.w * wv;
            acc[12] += e3.x * wv;  acc[13] += e3.y * wv;
            acc[14] += e3.z * wv;  acc[15] += e3.w * wv;
            acc[16] += ee   * wv;
        }
        __syncthreads();

        float* red = etr;
#pragma unroll
        for (int v = 0; v < V; v++) red[ty * (V * 8) + v * 8 + jl] = acc[v];
        __syncthreads();

        if (tid < V * 8) {
            const int j = jbase + (tid & 7);
            float s = b1[j];
#pragma unroll
            for (int g = 0; g < 64; g++) s += red[g * (V * 8) + tid];
            s = 0.5f * s * (1.0f + erff(s * 0.70710678118654752f));
            g_midT[j * EPAD + (tid >> 3)] = s;
        }
        __syncthreads();
        if (tid == 0) {
            __threadfence();               // release g_midT writes
            atomicAdd(&g_done, 1);
        }
        return;
    }

    // ================= consumer: hist -> wait -> GEMM2+mix =================
    const int jt = bid - 64;               // 0..63: also this CTA's column tile
    const int jbase = jt * 8;
    const int jl = tid & 7;
    const int ty = tid >> 3;

    // prelude independent of producers: W2 prefetch, b2, inv lens
    const float* wp = W2 + (size_t)(ty * 8) * D + jbase + jl;
    float w[8];
#pragma unroll
    for (int kk = 0; kk < 8; kk++) w[kk] = wp[kk * D];
    float b2v = 0.0f;
    if (tid < V * 8) b2v = b2[jbase + (tid & 7)];
    if (tid < n_segs) inv[tid] = 1.0f / (float)(cu[tid + 1] - cu[tid]);

    // histogram for segment jt (if it exists)
    if (jt < n_segs) {
        const int start = cu[jt];
        const int end = cu[jt + 1];
        const int wid = tid >> 5;
        for (int i = tid; i < 16 * 32; i += TPB) cnt[i] = 0;
        __syncthreads();
        for (int base = start + tid * 4; base < end; base += TPB * 4) {
            int t0 = -1, t1 = -1, t2 = -1, t3 = -1;
            if (base + 0 < end) t0 = tok[base + 0];
            if (base + 1 < end) t1 = tok[base + 1];
            if (base + 2 < end) t2 = tok[base + 2];
            if (base + 3 < end) t3 = tok[base + 3];
            if (t0 >= 0) atomicAdd(&cnt[wid * 32 + t0], 1);
            if (t1 >= 0) atomicAdd(&cnt[wid * 32 + t1], 1);
            if (t2 >= 0) atomicAdd(&cnt[wid * 32 + t2], 1);
            if (t3 >= 0) atomicAdd(&cnt[wid * 32 + t3], 1);
        }
        __syncthreads();
        if (tid < V) {
            int c = 0;
#pragma unroll
            for (int ww = 0; ww < 16; ww++) c += cnt[ww * 32 + tid];
            g_hist[jt][tid] = c;
        }
        __syncthreads();
    }

    // arrive (hist published), then wait for all 128 arrivals
    if (tid == 0) {
        __threadfence();                   // release g_hist writes
        atomicAdd(&g_done, 1);
        while (atomicAdd(&g_done, 0) < 128) __nanosleep(64);
        __threadfence();                   // acquire producers' writes
        atomicAdd(&g_ack, 1);              // passed the wait
    }
    __syncthreads();

    // counts -> fcs
    {
        const int i0 = tid, i1 = tid + TPB, i2 = tid + 2 * TPB;
        int c0 = 0, c1 = 0, c2 = 0;
        if (i0 < n_segs * V) c0 = ((const int*)g_hist)[i0];
        if (i1 < n_segs * V) c1 = ((const int*)g_hist)[i1];
        if (i2 < n_segs * V) c2 = ((const int*)g_hist)[i2];
        if (i0 < n_segs * V) fcs[(i0 / V) * 18 + (i0 % V)] = (float)c0;
        if (i1 < n_segs * V) fcs[(i1 / V) * 18 + (i1 % V)] = (float)c1;
        if (i2 < n_segs * V) fcs[(i2 / V) * 18 + (i2 % V)] = (float)c2;
    }

    // stage g_midT (5 fixed float4 LDG per thread)
    {
        const float4* M4 = (const float4*)g_midT;
        float4* S4 = (float4*)etr;
        const float4 m0 = M4[tid];
        const float4 m1 = M4[tid + 512];
        const float4 m2 = M4[tid + 1024];
        const float4 m3 = M4[tid + 1536];
        const float4 m4 = M4[tid + 2048];
        S4[tid] = m0;  S4[tid + 512] = m1;  S4[tid + 1024] = m2;
        S4[tid + 1536] = m3;  S4[tid + 2048] = m4;
    }
    __syncthreads();

    float acc[V];
#pragma unroll
    for (int v = 0; v < V; v++) acc[v] = 0.0f;

#pragma unroll
    for (int kk = 0; kk < 8; kk++) {
        const float* er = &etr[(ty * 8 + kk) * EPAD];
        const float4 e0 = *(const float4*)(er);
        const float4 e1 = *(const float4*)(er + 4);
        const float4 e2 = *(const float4*)(er + 8);
        const float4 e3 = *(const float4*)(er + 12);
        const float  ee = er[16];
        const float  wv = w[kk];
        acc[0]  += e0.x * wv;  acc[1]  += e0.y * wv;
        acc[2]  += e0.z * wv;  acc[3]  += e0.w * wv;
        acc[4]  += e1.x * wv;  acc[5]  += e1.y * wv;
        acc[6]  += e1.z * wv;  acc[7]  += e1.w * wv;
        acc[8]  += e2.x * wv;  acc[9]  += e2.y * wv;
        acc[10] += e2.z * wv;  acc[11] += e2.w * wv;
        acc[12] += e3.x * wv;  acc[13] += e3.y * wv;
        acc[14] += e3.z * wv;  acc[15] += e3.w * wv;
        acc[16] += ee   * wv;
    }
    __syncthreads();

    float* red = etr;
#pragma unroll
    for (int v = 0; v < V; v++) red[ty * (V * 8) + v * 8 + jl] = acc[v];
    __syncthreads();

    if (tid < V * 8) {
        float s = b2v;
#pragma unroll
        for (int g = 0; g < 64; g++) s += red[g * (V * 8) + tid];
        Ht[tid] = s;
    }
    __syncthreads();

    const int sseg = tid >> 3;
    if (sseg < n_segs) {
        const float* f = &fcs[sseg * 18];
        float a = 0.0f;
#pragma unroll
        for (int v = 0; v < V; v++) a += f[v] * Ht[v * 8 + jl];
        out[sseg * D + jbase + jl] = a * inv[sseg];
    }

    // counter reset for next launch/replay: CTA 64 waits until every consumer
    // has passed the wait (acked), then zeroes. No one reads g_done/g_ack
    // again this launch, so plain stores are safe.
    if (jt == 0) {
        __syncthreads();
        if (tid == 0) {
            while (atomicAdd(&g_ack, 0) < 64) __nanosleep(64);
            g_done = 0;
            g_ack = 0;
            __threadfence();
        }
    }
}

// ---------------------------------------------------------------------------
extern "C" void kernel_launch(void* const* d_in, const int* in_sizes, int n_in,
                              void* d_out, int out_size) {
    const int*   tok = (const int*)  d_in[0];
    const int*   cu  = (const int*)  d_in[1];
    const float* E   = (const float*)d_in[2];
    const float* W1  = (const float*)d_in[3];
    const float* b1  = (const float*)d_in[4];
    const float* W2  = (const float*)d_in[5];
    const float* b2  = (const float*)d_in[6];
    float*       out = (float*)d_out;

    int n_segs = in_sizes[1] - 1;
    if (n_segs > MAX_SEGS) n_segs = MAX_SEGS;

    fused<<<128, TPB>>>(E, W1, b1, W2, b2, tok, cu, out, n_segs);
}

// round 16
// speedup vs baseline: 1.1196x; 1.1196x over previous
#include <cuda_runtime.h>
#include <math.h>

#define D 512
#define V 17
#define MAX_SEGS 64
#define EPAD 20
#define KS 4            // k-slices in GEMM1
#define KSL 128
#define TPB 512

// Scratch (allocation-free, graph-safe).
__device__ float g_part1[KS][V][D];        // partial E@W1
__device__ float g_midT[D * EPAD];         // finalized gelu-mid, transposed+padded
__device__ int   g_hist[MAX_SEGS][V];      // per-segment token counts

// k1 shared scratch (max member 34816 B)
union SmemU {
    float etr[KSL * EPAD];      // transposed E k-slice (10240B)
    float red[16 * V * 32];     // split-slice reduction (34816B)
    int   cnt[16 * 32];         // per-warp histograms
};

// ---------------------------------------------------------------------------
// k1: CTAs 0..63: partial GEMM1 (jt x ks = 16 x 4). CTAs 64..: histograms,
// which afterwards prefetch their 1/64 slice of W2 into L2 for k2.
// ---------------------------------------------------------------------------
__global__ void __launch_bounds__(TPB, 1)
k1(const float* __restrict__ E, const float* __restrict__ W1,
   const int* __restrict__ tok, const int* __restrict__ cu,
   const float* __restrict__ W2, int n_segs) {
    __shared__ SmemU sm;
    const int bid = blockIdx.x;
    const int tid = threadIdx.x;

    if (bid < 64) {
        const int jt = bid >> 2;
        const int ks = bid & 3;
        const int tx = tid & 31;
        const int ty = tid >> 5;

        // stage E k-slice transposed: one float4 LDG per thread (+tail)
        const float4* E4 = (const float4*)E;
        if (tid < V * 32) {
            const int v = tid >> 5;
            const int q = tid & 31;
            const float4 e = E4[v * (D / 4) + ks * 32 + q];
            const int kl = q * 4;
            sm.etr[(kl + 0) * EPAD + v] = e.x;
            sm.etr[(kl + 1) * EPAD + v] = e.y;
            sm.etr[(kl + 2) * EPAD + v] = e.z;
            sm.etr[(kl + 3) * EPAD + v] = e.w;
        }
        if (tid < V * 32 - TPB) {
            const int i = TPB + tid;
            const int v = i >> 5;
            const int q = i & 31;
            const float4 e = E4[v * (D / 4) + ks * 32 + q];
            const int kl = q * 4;
            sm.etr[(kl + 0) * EPAD + v] = e.x;
            sm.etr[(kl + 1) * EPAD + v] = e.y;
            sm.etr[(kl + 2) * EPAD + v] = e.z;
            sm.etr[(kl + 3) * EPAD + v] = e.w;
        }
        __syncthreads();

        float acc[V];
#pragma unroll
        for (int v = 0; v < V; v++) acc[v] = 0.0f;

        const float* wp = W1 + (size_t)(ks * KSL + ty * 8) * D + jt * 32 + tx;
        float w[8];
#pragma unroll
        for (int kk = 0; kk < 8; kk++) w[kk] = wp[kk * D];

#pragma unroll
        for (int kk = 0; kk < 8; kk++) {
            const float* er = &sm.etr[(ty * 8 + kk) * EPAD];
            const float4 e0 = *(const float4*)(er);
            const float4 e1 = *(const float4*)(er + 4);
            const float4 e2 = *(const float4*)(er + 8);
            const float4 e3 = *(const float4*)(er + 12);
            const float  ee = er[16];
            const float  wv = w[kk];
            acc[0]  += e0.x * wv;  acc[1]  += e0.y * wv;
            acc[2]  += e0.z * wv;  acc[3]  += e0.w * wv;
            acc[4]  += e1.x * wv;  acc[5]  += e1.y * wv;
            acc[6]  += e1.z * wv;  acc[7]  += e1.w * wv;
            acc[8]  += e2.x * wv;  acc[9]  += e2.y * wv;
            acc[10] += e2.z * wv;  acc[11] += e2.w * wv;
            acc[12] += e3.x * wv;  acc[13] += e3.y * wv;
            acc[14] += e3.z * wv;  acc[15] += e3.w * wv;
            acc[16] += ee   * wv;
        }
        __syncthreads();

#pragma unroll
        for (int v = 0; v < V; v++) sm.red[(ty * V + v) * 32 + tx] = acc[v];
        __syncthreads();

        for (int o = tid; o < V * 32; o += TPB) {
            const int v = o >> 5;
            const int t = o & 31;
            float s = 0.0f;
#pragma unroll
            for (int sl = 0; sl < 16; sl++) s += sm.red[(sl * V + v) * 32 + t];
            g_part1[ks][v][jt * 32 + t] = s;
        }
        return;
    }

    const int s = bid - 64;
    if (s >= n_segs) {
        return;
    }
    const int start = cu[s];
    const int end = cu[s + 1];
    const int wid = tid >> 5;

    for (int i = tid; i < 16 * 32; i += TPB) sm.cnt[i] = 0;
    __syncthreads();
    for (int base = start + tid * 4; base < end; base += TPB * 4) {
        int t0 = -1, t1 = -1, t2 = -1, t3 = -1;
        if (base + 0 < end) t0 = tok[base + 0];
        if (base + 1 < end) t1 = tok[base + 1];
        if (base + 2 < end) t2 = tok[base + 2];
        if (base + 3 < end) t3 = tok[base + 3];
        if (t0 >= 0) atomicAdd(&sm.cnt[wid * 32 + t0], 1);
        if (t1 >= 0) atomicAdd(&sm.cnt[wid * 32 + t1], 1);
        if (t2 >= 0) atomicAdd(&sm.cnt[wid * 32 + t2], 1);
        if (t3 >= 0) atomicAdd(&sm.cnt[wid * 32 + t3], 1);
    }
    __syncthreads();
    if (tid < V) {
        int c = 0;
#pragma unroll
        for (int w = 0; w < 16; w++) c += sm.cnt[w * 32 + tid];
        g_hist[s][tid] = c;
    }

    // warm L2 with this CTA's 1/64 slice of W2 (65536 float4 total / 64 = 1024)
    {
        const float4* W24 = (const float4*)W2;
#pragma unroll
        for (int r = 0; r < 2; r++) {
            const float4* p = W24 + (size_t)s * 1024 + r * TPB + tid;
            asm volatile("prefetch.global.L2 [%0];" :: "l"(p));
        }
    }
}

// ---------------------------------------------------------------------------
// kmid: finalize mid = gelu(E@W1+b1) into transposed padded g_midT[k*20+v].
// 17 CTAs x 512 threads = 8704 = V*D elements, one each.
// ---------------------------------------------------------------------------
__global__ void __launch_bounds__(TPB, 1)
kmid(const float* __restrict__ b1) {
    const int i = blockIdx.x * TPB + threadIdx.x;   // < V*D
    const int v = i >> 9;
    const int k = i & 511;
    float s = b1[k] + g_part1[0][v][k] + g_part1[1][v][k]
                    + g_part1[2][v][k] + g_part1[3][v][k];
    s = 0.5f * s * (1.0f + erff(s * 0.70710678118654752f));
    g_midT[k * EPAD + v] = s;
}

// ---------------------------------------------------------------------------
// k2: 64 CTAs x 8 output columns, full-K GEMM2 + segment mix + store.
// Clean g_midT staging; two-stage (32+32, then 2) deterministic k-reduction.
// Static smem: 40960 + 2176 + 4608 + 256 = 48000 B.
// ---------------------------------------------------------------------------
__global__ void __launch_bounds__(TPB, 1)
k2(const float* __restrict__ W2, const float* __restrict__ b2,
   const int* __restrict__ cu, float* __restrict__ out, int n_segs) {
    __shared__ float etr[D * EPAD];            // stage buffer, then reduction
    __shared__ float Ht[V * 8 * 4];
    __shared__ float fcs[MAX_SEGS * 18];
    __shared__ float inv[MAX_SEGS];

    const int bid = blockIdx.x;
    const int tid = threadIdx.x;
    const int jl = tid & 7;
    const int ty = tid >> 3;                   // 0..63
    const int jbase = bid * 8;

    // overlap: segment counts + inverse lengths
    {
        const int i0 = tid, i1 = tid + TPB, i2 = tid + 2 * TPB;
        int c0 = 0, c1 = 0, c2 = 0;
        if (i0 < n_segs * V) c0 = ((const int*)g_hist)[i0];
        if (i1 < n_segs * V) c1 = ((const int*)g_hist)[i1];
        if (i2 < n_segs * V) c2 = ((const int*)g_hist)[i2];
        if (i0 < n_segs * V) fcs[(i0 / V) * 18 + (i0 % V)] = (float)c0;
        if (i1 < n_segs * V) fcs[(i1 / V) * 18 + (i1 % V)] = (float)c1;
        if (i2 < n_segs * V) fcs[(i2 / V) * 18 + (i2 % V)] = (float)c2;
        if (tid < n_segs) inv[tid] = 1.0f / (float)(cu[tid + 1] - cu[tid]);
    }

    // stage full transposed mid table: 5 fixed float4 LDG per thread
    {
        const float4* M4 = (const float4*)g_midT;
        float4* S4 = (float4*)etr;
        const float4 m0 = M4[tid];
        const float4 m1 = M4[tid + 512];
        const float4 m2 = M4[tid + 1024];
        const float4 m3 = M4[tid + 1536];
        const float4 m4 = M4[tid + 2048];
        S4[tid] = m0;  S4[tid + 512] = m1;  S4[tid + 1024] = m2;
        S4[tid + 1536] = m3;  S4[tid + 2048] = m4;
    }
    __syncthreads();

    float acc[V];
#pragma unroll
    for (int v = 0; v < V; v++) acc[v] = 0.0f;

    const float* wp = W2 + (size_t)(ty * 8) * D + jbase + jl;   // L2-hot via k1
    float w[8];
#pragma unroll
    for (int kk = 0; kk < 8; kk++) w[kk] = wp[kk * D];

#pragma unroll
    for (int kk = 0; kk < 8; kk++) {
        const float* er = &etr[(ty * 8 + kk) * EPAD];
        const float4 e0 = *(const float4*)(er);
        const float4 e1 = *(const float4*)(er + 4);
        const float4 e2 = *(const float4*)(er + 8);
        const float4 e3 = *(const float4*)(er + 12);
        const float  ee = er[16];
        const float  wv = w[kk];
        acc[0]  += e0.x * wv;  acc[1]  += e0.y * wv;
        acc[2]  += e0.z * wv;  acc[3]  += e0.w * wv;
        acc[4]  += e1.x * wv;  acc[5]  += e1.y * wv;
        acc[6]  += e1.z * wv;  acc[7]  += e1.w * wv;
        acc[8]  += e2.x * wv;  acc[9]  += e2.y * wv;
        acc[10] += e2.z * wv;  acc[11] += e2.w * wv;
        acc[12] += e3.x * wv;  acc[13] += e3.y * wv;
        acc[14] += e3.z * wv;  acc[15] += e3.w * wv;
        acc[16] += ee   * wv;
    }
    __syncthreads();           // done reading etr; reuse as reduction buffer

    float* red = etr;          // [64][V*8] = 8704 floats; parts at [8704..8976)
#pragma unroll
    for (int v = 0; v < V; v++) red[ty * (V * 8) + v * 8 + jl] = acc[v];
    __syncthreads();

    // stage 1: 272 threads, each sums one 32-group half for one output
    if (tid < V * 8 * 2) {
        const int o = tid >> 1;        // 0..135
        const int h = tid & 1;         // half
        float s = 0.0f;
#pragma unroll
        for (int g = 0; g < 32; g++) s += red[(h * 32 + g) * (V * 8) + o];
        red[64 * (V * 8) + o * 2 + h] = s;
    }
    __syncthreads();

    // stage 2: 136 threads finish (fixed order -> deterministic)
    if (tid < V * 8) {
        float s = b2[jbase + (tid & 7)]
                + red[64 * (V * 8) + tid * 2]
                + red[64 * (V * 8) + tid * 2 + 1];
        Ht[tid] = s;
    }
    __syncthreads();

    const int s = tid >> 3;
    if (s < n_segs) {
        const float* f = &fcs[s * 18];
        float a = 0.0f;
#pragma unroll
        for (int v = 0; v < V; v++) a += f[v] * Ht[v * 8 + jl];
        out[s * D + jbase + jl] = a * inv[s];
    }
}

// ---------------------------------------------------------------------------
extern "C" void kernel_launch(void* const* d_in, const int* in_sizes, int n_in,
                              void* d_out, int out_size) {
    const int*   tok = (const int*)  d_in[0];
    const int*   cu  = (const int*)  d_in[1];
    const float* E   = (const float*)d_in[2];
    const float* W1  = (const float*)d_in[3];
    const float* b1  = (const float*)d_in[4];
    const float* W2  = (const float*)d_in[5];
    const float* b2  = (const float*)d_in[6];
    float*       out = (float*)d_out;

    int n_segs = in_sizes[1] - 1;
    if (n_segs > MAX_SEGS) n_segs = MAX_SEGS;

    k1<<<64 + n_segs, TPB>>>(E, W1, tok, cu, W2, n_segs);
    kmid<<<V, TPB>>>(b1);
    k2<<<64, TPB>>>(W2, b2, cu, out, n_segs);
}